// round 13
// baseline (speedup 1.0000x reference)
#include <cuda_runtime.h>
#include <cuda_fp16.h>
#include <math.h>
#include <stdint.h>

// ===========================================================================
// FFNerf fused inference via mma.sync.m16n8k16.f16.
//
// R13: CTA-wide __syncthreads at layer boundaries replaced by 64-thread
// named pair-barriers (warps {wm, wm+4} share an m-tile; they are the only
// cross-warp hazard since each warp reads/writes only its own 16 A-rows).
// Full syncs remain only around posenc and L5's X-overwrite (cross-pair).
// Retains: 2-mma split (act hi/lo fp16 x fp16 weights), paired-B uint4 image
// (one LDG.128 feeds 4 mma), single in-place A buffer (53KB smem, 3 CTAs/SM),
// ldmatrix.x4 A-fragments, two-pass mma order, fused prep kernel.
//
// Per CTA: 64 points, 256 threads = 8 warps (4 M-warps x 2 N-warps).
// sigma folded into L8 (w23 padded to N=160; col 128 = sigma).
// Color head via mma (N pad 16). Output: color (3N) then sigma (N).
// ===========================================================================

constexpr int MPTS     = 64;
constexpr int NTHREADS = 256;

constexpr int AP = 136;   // A pitch (halves); 272B rows: 16B-aligned, bank-stride 4
constexpr int XP = 72;    // X pitch (halves)

// smem half-index offsets (single A + X)
constexpr int S_AHI = 0;
constexpr int S_ALO = S_AHI + MPTS * AP;      // 8704
constexpr int S_XHI = S_ALO + MPTS * AP;      // 17408
constexpr int S_XLO = S_XHI + MPTS * XP;      // 22016
constexpr int SMEM_HALVES = S_XLO + MPTS * XP;  // 26624
constexpr int SMEM_BYTES  = SMEM_HALVES * 2;    // 53248 -> 3 CTAs/SM

// weight image section offsets (uint4 units); size = NKS*NTP*32
// uint4 = {bh0(nt),bh1(nt),bh0(nt+1),bh1(nt+1)} for n-tile pair ntp.
constexpr int O_L0   = 0;        // NKS4  NTP8  -> 1024
constexpr int O_L1   = 1024;     // NKS8  NTP8  -> 2048
constexpr int O_L2   = 3072;
constexpr int O_L3   = 5120;
constexpr int O_L4   = 7168;
constexpr int O_L5A  = 9216;     // 2048
constexpr int O_L5X  = 11264;    // NKS4  NTP8  -> 1024
constexpr int O_L6   = 12288;
constexpr int O_L7   = 14336;
constexpr int O_L8   = 16384;    // NKS8  NTP10 -> 2560 (N pad 160, col128=sigma)
constexpr int O_L9A  = 18944;    // NKS8  NTP4  -> 1024
constexpr int O_L9X  = 19968;    // NKS2  NTP4  -> 256
constexpr int O_HEAD = 20224;    // NKS4  NTP1  -> 128 (N pad 16)
constexpr int IMG_TOTAL = 20352; // uint4 -> 326 KB

__device__ uint4 g_img[IMG_TOTAL];

// Pair barrier: warps {wm, wm+4} (the two N-warps of one m-tile), 64 threads.
// Named barrier ids 1..4 (0 belongs to __syncthreads).
#define PAIR_BAR(wm) \
    asm volatile("bar.sync %0, 64;" :: "r"((wm) + 1) : "memory")

// ---------------- fused prep: pack paired per-lane B-hi fragments ----------
__device__ __forceinline__ uint32_t pack_h2(__half a, __half b) {
    __half2 v = __halves2half2(a, b);
    return *reinterpret_cast<uint32_t*>(&v);
}

__global__ void prep_all_kernel(
    const float* w10, const float* w11, const float* w12, const float* w13,
    const float* w14, const float* w20, const float* w21, const float* w22,
    const float* w23, const float* w30, const float* w31)
{
    int idx = blockIdx.x * blockDim.x + threadIdx.x;
    if (idx >= IMG_TOTAL) return;

    const int offs[14] = { O_L0, O_L1, O_L2, O_L3, O_L4, O_L5A, O_L5X,
                           O_L6, O_L7, O_L8, O_L9A, O_L9X, O_HEAD, IMG_TOTAL };
    const float* srcs[13] = { w10, w11, w12, w13, w14, w20, w20,
                              w21, w22, w23, w30, w30, w31 };
    //                       pitch kReal row0 nMax NTP
    const int cfg[13][5] = {
        { 128,  63,   0, 128,  8 },   // L0
        { 128, 128,   0, 128,  8 },   // L1
        { 128, 128,   0, 128,  8 },   // L2
        { 128, 128,   0, 128,  8 },   // L3
        { 128, 128,   0, 128,  8 },   // L4
        { 128, 128,   0, 128,  8 },   // L5A
        { 128,  63, 128, 128,  8 },   // L5X
        { 128, 128,   0, 128,  8 },   // L6
        { 128, 128,   0, 128,  8 },   // L7
        { 129, 128,   0, 129, 10 },   // L8
        {  64, 128,   0,  64,  4 },   // L9A
        {  64,  27, 128,  64,  4 },   // L9X
        {   3,  64,   0,   3,  1 },   // HEAD
    };

    int s = 0;
    while (idx >= offs[s + 1]) ++s;
    int local = idx - offs[s];
    const float* src = srcs[s];
    const int pitch = cfg[s][0], kReal = cfg[s][1], row0 = cfg[s][2];
    const int nMax  = cfg[s][3], NTP   = cfg[s][4];

    int lane = local & 31;
    int rest = local >> 5;
    int ntp  = rest % NTP;
    int ks   = rest / NTP;
    int g = lane >> 2, t = lane & 3;
    int kk[4] = { ks*16 + 2*t, ks*16 + 2*t + 1, ks*16 + 2*t + 8, ks*16 + 2*t + 9 };

    uint32_t packed[2][2];
    #pragma unroll
    for (int half = 0; half < 2; ++half) {
        int n = (ntp * 2 + half) * 8 + g;
        __half h[4];
        #pragma unroll
        for (int j = 0; j < 4; ++j) {
            float w = (kk[j] < kReal && n < nMax)
                        ? src[(row0 + kk[j]) * pitch + n] : 0.f;
            h[j] = __float2half_rn(w);
        }
        packed[half][0] = pack_h2(h[0], h[1]);
        packed[half][1] = pack_h2(h[2], h[3]);
    }
    g_img[idx] = make_uint4(packed[0][0], packed[0][1],
                            packed[1][0], packed[1][1]);
}

// ---------------- mma / ldmatrix -------------------------------------------
__device__ __forceinline__ uint32_t smem_u32(const void* p) {
    uint32_t a;
    asm("{ .reg .u64 t; cvta.to.shared.u64 t, %1; cvt.u32.u64 %0, t; }"
        : "=r"(a) : "l"(p));
    return a;
}

#define LDSM_X4(r, addr) \
    asm volatile("ldmatrix.sync.aligned.m8n8.x4.shared.b16 {%0,%1,%2,%3}, [%4];" \
        : "=r"((r)[0]), "=r"((r)[1]), "=r"((r)[2]), "=r"((r)[3]) : "r"(addr))

__device__ __forceinline__ void mma16816(float* c, const uint32_t* a,
                                         uint32_t b0, uint32_t b1) {
    asm volatile(
        "mma.sync.aligned.m16n8k16.row.col.f32.f16.f16.f32 "
        "{%0,%1,%2,%3}, {%4,%5,%6,%7}, {%8,%9}, {%0,%1,%2,%3};"
        : "+f"(c[0]), "+f"(c[1]), "+f"(c[2]), "+f"(c[3])
        : "r"(a[0]), "r"(a[1]), "r"(a[2]), "r"(a[3]), "r"(b0), "r"(b1));
}

// Accumulate NKS k-steps x NT n-tiles (NT even). Per pair: one LDG.128 of
// paired B-hi fragments feeds 4 mma. Two passes per k-step (al over all
// tiles, then ah) so consecutive mma never share an accumulator.
template <int NKS, int NT>
__device__ __forceinline__ void mma_loop(
    float (*c)[4], const __half* Hi, const __half* Lo, int P,
    const uint4* __restrict__ img, int NTPG, int ntp0, int m0, int lane)
{
    constexpr int NP = NT / 2;
    const int mat = lane >> 3, rin = lane & 7;
    const int row = m0 + rin + 8 * (mat & 1);
    const int colk = 8 * (mat >> 1);
    const uint32_t aHi = smem_u32(Hi + row * P + colk);
    const uint32_t aLo = smem_u32(Lo + row * P + colk);
    #pragma unroll
    for (int ks = 0; ks < NKS; ++ks) {
        uint32_t ah[4], al[4];
        LDSM_X4(al, aLo + ks * 32);
        LDSM_X4(ah, aHi + ks * 32);
        const uint4* ib = img + (ks * NTPG + ntp0) * 32 + lane;
        uint4 b[NP];
        #pragma unroll
        for (int j = 0; j < NP; ++j) b[j] = __ldg(ib + j * 32);
        #pragma unroll
        for (int j = 0; j < NP; ++j) {
            mma16816(c[2*j],     al, b[j].x, b[j].y);
            mma16816(c[2*j + 1], al, b[j].z, b[j].w);
        }
        #pragma unroll
        for (int j = 0; j < NP; ++j) {
            mma16816(c[2*j],     ah, b[j].x, b[j].y);
            mma16816(c[2*j + 1], ah, b[j].z, b[j].w);
        }
    }
}

// Split-store a pair (cols col, col+1) at half-index idx (packed cvt).
__device__ __forceinline__ void store_split(__half* Hi, __half* Lo, int idx,
                                            float v0, float v1) {
    __half2 hp = __float22half2_rn(make_float2(v0, v1));
    float2 hf = __half22float2(hp);
    __half2 lp = __float22half2_rn(make_float2(v0 - hf.x, v1 - hf.y));
    *reinterpret_cast<__half2*>(Hi + idx) = hp;
    *reinterpret_cast<__half2*>(Lo + idx) = lp;
}

template <int NT, bool RELU>
__device__ __forceinline__ void write_act(
    float (*c)[4], __half* Hi, __half* Lo, int P, int nt0, int m0, int lane)
{
    const int g = lane >> 2, t = lane & 3;
    const int r0 = (m0 + g) * P;
    const int r1 = r0 + 8 * P;
    #pragma unroll
    for (int nt = 0; nt < NT; ++nt) {
        int col = (nt0 + nt) * 8 + 2 * t;
        float v0 = c[nt][0], v1 = c[nt][1], v2 = c[nt][2], v3 = c[nt][3];
        if (RELU) {
            v0 = fmaxf(v0, 0.f); v1 = fmaxf(v1, 0.f);
            v2 = fmaxf(v2, 0.f); v3 = fmaxf(v3, 0.f);
        }
        store_split(Hi, Lo, r0 + col, v0, v1);
        store_split(Hi, Lo, r1 + col, v2, v3);
    }
}

__device__ __forceinline__ void put_x(__half* XHi, __half* XLo, int row,
                                      int col, float v) {
    int idx = row * XP + col;
    __half h = __float2half_rn(v);
    XHi[idx] = h;
    XLo[idx] = __float2half_rn(v - __half2float(h));
}

// ---------------- main kernel ----------------------------------------------
__global__ void __launch_bounds__(NTHREADS, 3)
ffnerf_hmma_kernel(const float* __restrict__ pos,
                   const float* __restrict__ dirs,
                   float* __restrict__ out, int npts)
{
    extern __shared__ __half smh[];
    __half* AHi = smh + S_AHI;
    __half* ALo = smh + S_ALO;
    __half* XHi = smh + S_XHI;
    __half* XLo = smh + S_XLO;

    const int tid  = threadIdx.x;
    const int lane = tid & 31;
    const int warp = tid >> 5;
    const int g    = lane >> 2;
    const int t    = lane & 3;
    const int wm   = warp & 3;
    const int wn   = warp >> 2;
    const int m0   = wm * 16;
    const int g0   = blockIdx.x * MPTS;

    // --- posenc x_emb (63 features, col 63 zero) ---------------------------
    if (tid < MPTS) {
        int gp = g0 + tid;
        float p0 = pos[gp*3+0], p1 = pos[gp*3+1], p2 = pos[gp*3+2];
        put_x(XHi, XLo, tid, 0, p0);
        put_x(XHi, XLo, tid, 1, p1);
        put_x(XHi, XLo, tid, 2, p2);
        #pragma unroll
        for (int j = 0; j < 10; ++j) {
            float f = (float)(1 << j);
            float s0, c0, s1, c1, s2, c2;
            sincosf(f * p0, &s0, &c0);
            sincosf(f * p1, &s1, &c1);
            sincosf(f * p2, &s2, &c2);
            put_x(XHi, XLo, tid, 3 + 6*j + 0, s0);
            put_x(XHi, XLo, tid, 3 + 6*j + 1, s1);
            put_x(XHi, XLo, tid, 3 + 6*j + 2, s2);
            put_x(XHi, XLo, tid, 3 + 6*j + 3, c0);
            put_x(XHi, XLo, tid, 3 + 6*j + 4, c1);
            put_x(XHi, XLo, tid, 3 + 6*j + 5, c2);
        }
        put_x(XHi, XLo, tid, 63, 0.f);
    }
    __syncthreads();   // X visible to all pairs

    // --- L0: x_emb(64) -> 128, relu (A unwritten before: no pre-barrier) --
    {
        float c[8][4];
        #pragma unroll
        for (int i = 0; i < 8; ++i)
            #pragma unroll
            for (int j = 0; j < 4; ++j) c[i][j] = 0.f;
        mma_loop<4, 8>(c, XHi, XLo, XP, g_img + O_L0, 8, wn * 4, m0, lane);
        write_act<8, true>(c, AHi, ALo, AP, wn * 8, m0, lane);
        PAIR_BAR(wm);
    }

    // --- L1..L4: 128 -> 128, relu (in-place A, pair-scoped hazards) -------
    const int mids[4] = { O_L1, O_L2, O_L3, O_L4 };
    #pragma unroll
    for (int li = 0; li < 4; ++li) {
        float c[8][4];
        #pragma unroll
        for (int i = 0; i < 8; ++i)
            #pragma unroll
            for (int j = 0; j < 4; ++j) c[i][j] = 0.f;
        mma_loop<8, 8>(c, AHi, ALo, AP, g_img + mids[li], 8, wn * 4, m0, lane);
        PAIR_BAR(wm);
        write_act<8, true>(c, AHi, ALo, AP, wn * 8, m0, lane);
        PAIR_BAR(wm);
    }

    // --- L5: [h | x_emb](192) -> 128, relu; then d_emb into X -------------
    // X rows are read cross-pair (warp wm reads rows written by warps 0/1),
    // so the X-overwrite needs FULL syncs on both sides.
    {
        float c[8][4];
        #pragma unroll
        for (int i = 0; i < 8; ++i)
            #pragma unroll
            for (int j = 0; j < 4; ++j) c[i][j] = 0.f;
        mma_loop<8, 8>(c, AHi, ALo, AP, g_img + O_L5A, 8, wn * 4, m0, lane);
        mma_loop<4, 8>(c, XHi, XLo, XP, g_img + O_L5X, 8, wn * 4, m0, lane);
        __syncthreads();   // all X reads done before d_emb overwrite
        write_act<8, true>(c, AHi, ALo, AP, wn * 8, m0, lane);
        // d_emb posenc (27 features, cols 27..31 zero)
        if (tid < MPTS) {
            int gp = g0 + tid;
            float d0 = dirs[gp*3+0], d1 = dirs[gp*3+1], d2 = dirs[gp*3+2];
            put_x(XHi, XLo, tid, 0, d0);
            put_x(XHi, XLo, tid, 1, d1);
            put_x(XHi, XLo, tid, 2, d2);
            #pragma unroll
            for (int j = 0; j < 4; ++j) {
                float f = (float)(1 << j);
                float s0, c0, s1, c1, s2, c2;
                sincosf(f * d0, &s0, &c0);
                sincosf(f * d1, &s1, &c1);
                sincosf(f * d2, &s2, &c2);
                put_x(XHi, XLo, tid, 3 + 6*j + 0, s0);
                put_x(XHi, XLo, tid, 3 + 6*j + 1, s1);
                put_x(XHi, XLo, tid, 3 + 6*j + 2, s2);
                put_x(XHi, XLo, tid, 3 + 6*j + 3, c0);
                put_x(XHi, XLo, tid, 3 + 6*j + 4, c1);
                put_x(XHi, XLo, tid, 3 + 6*j + 5, c2);
            }
            #pragma unroll
            for (int z = 27; z < 32; ++z) put_x(XHi, XLo, tid, z, 0.f);
        }
        __syncthreads();   // A writes + d_emb visible to all
    }

    // --- L6, L7: 128 -> 128, relu -----------------------------------------
    #pragma unroll
    for (int li = 0; li < 2; ++li) {
        float c[8][4];
        #pragma unroll
        for (int i = 0; i < 8; ++i)
            #pragma unroll
            for (int j = 0; j < 4; ++j) c[i][j] = 0.f;
        mma_loop<8, 8>(c, AHi, ALo, AP, g_img + (li == 0 ? O_L6 : O_L7), 8,
                       wn * 4, m0, lane);
        PAIR_BAR(wm);
        write_act<8, true>(c, AHi, ALo, AP, wn * 8, m0, lane);
        PAIR_BAR(wm);
    }

    // --- L8: 128 -> 160-pad (feat cols 0..127 linear, col 128 = sigma) ----
    {
        float c[10][4];
        #pragma unroll
        for (int i = 0; i < 10; ++i)
            #pragma unroll
            for (int j = 0; j < 4; ++j) c[i][j] = 0.f;
        mma_loop<8, 10>(c, AHi, ALo, AP, g_img + O_L8, 10, wn * 5, m0, lane);
        PAIR_BAR(wm);
        const int r0 = (m0 + g) * AP;
        const int r1 = r0 + 8 * AP;
        float* sigma = out + (size_t)3 * npts + g0;
        #pragma unroll
        for (int nt = 0; nt < 10; ++nt) {
            int colb = (wn * 10 + nt) * 8;
            if (colb < 128) {                       // feat, linear
                int col = colb + 2 * t;
                store_split(AHi, ALo, r0 + col, c[nt][0], c[nt][1]);
                store_split(AHi, ALo, r1 + col, c[nt][2], c[nt][3]);
            } else if (colb == 128 && t == 0) {     // sigma column
                sigma[m0 + g]     = fmaxf(c[nt][0], 0.f);
                sigma[m0 + g + 8] = fmaxf(c[nt][2], 0.f);
            }
        }
        PAIR_BAR(wm);
    }

    // --- L9: [feat | d_emb] -> 64, relu -----------------------------------
    {
        float c[4][4];
        #pragma unroll
        for (int i = 0; i < 4; ++i)
            #pragma unroll
            for (int j = 0; j < 4; ++j) c[i][j] = 0.f;
        mma_loop<8, 4>(c, AHi, ALo, AP, g_img + O_L9A, 4, wn * 2, m0, lane);
        mma_loop<2, 4>(c, XHi, XLo, XP, g_img + O_L9X, 4, wn * 2, m0, lane);
        PAIR_BAR(wm);
        write_act<4, true>(c, AHi, ALo, AP, wn * 4, m0, lane);
        PAIR_BAR(wm);
    }

    // --- head: 64 -> 3 (pad 16), sigmoid -> color -------------------------
    // Reads A rows m0..m0+15 cols 0..63 (both halves written by this pair;
    // ordered by the last PAIR_BAR).
    if (wn == 0) {
        float c[2][4];
        #pragma unroll
        for (int i = 0; i < 2; ++i)
            #pragma unroll
            for (int j = 0; j < 4; ++j) c[i][j] = 0.f;
        mma_loop<4, 2>(c, AHi, ALo, AP, g_img + O_HEAD, 1, 0, m0, lane);
        int row0 = g0 + m0 + g;
        int row1 = row0 + 8;
        if (t == 0) {
            out[row0*3 + 0] = 1.f / (1.f + expf(-c[0][0]));
            out[row0*3 + 1] = 1.f / (1.f + expf(-c[0][1]));
            out[row1*3 + 0] = 1.f / (1.f + expf(-c[0][2]));
            out[row1*3 + 1] = 1.f / (1.f + expf(-c[0][3]));
        } else if (t == 1) {
            out[row0*3 + 2] = 1.f / (1.f + expf(-c[0][0]));
            out[row1*3 + 2] = 1.f / (1.f + expf(-c[0][2]));
        }
    }
}

// ---------------- launch ----------------------------------------------------
extern "C" void kernel_launch(void* const* d_in, const int* in_sizes, int n_in,
                              void* d_out, int out_size)
{
    const float* pos  = (const float*)d_in[0];
    const float* dirs = (const float*)d_in[1];
    const float* w10  = (const float*)d_in[2];
    const float* w11  = (const float*)d_in[3];
    const float* w12  = (const float*)d_in[4];
    const float* w13  = (const float*)d_in[5];
    const float* w14  = (const float*)d_in[6];
    const float* w20  = (const float*)d_in[7];
    const float* w21  = (const float*)d_in[8];
    const float* w22  = (const float*)d_in[9];
    const float* w23  = (const float*)d_in[10];
    const float* w30  = (const float*)d_in[11];
    const float* w31  = (const float*)d_in[12];

    int npts = in_sizes[0] / 3;
    int nblocks = npts / MPTS;

    prep_all_kernel<<<(IMG_TOTAL + 255) / 256, 256>>>(
        w10, w11, w12, w13, w14, w20, w21, w22, w23, w30, w31);

    cudaFuncSetAttribute(ffnerf_hmma_kernel,
                         cudaFuncAttributeMaxDynamicSharedMemorySize, SMEM_BYTES);
    ffnerf_hmma_kernel<<<nblocks, NTHREADS, SMEM_BYTES>>>(
        pos, dirs, (float*)d_out, npts);
    (void)n_in; (void)out_size;
}

// round 15
// speedup vs baseline: 1.0289x; 1.0289x over previous
#include <cuda_runtime.h>
#include <cuda_fp16.h>
#include <math.h>
#include <stdint.h>

// ===========================================================================
// FFNerf fused inference via mma.sync.m16n8k16.f16.
//
// R15 = R14 + the missing `tid < MPTS` guards on both posenc blocks (the
// unguarded writes past X's 128 rows caused R14's illegal memory access).
//
// M_w=2: each warp owns TWO m-tiles (MPTS=128/CTA), so every B-fragment
// LDG.128 feeds 8 mma instead of 4 (L1 wavefronts/mma: 1.5 -> 1.0).
// X (posenc) stored fp16-hi only -> X-layers are single-pass mma and smem
// stays at 88KB (2 CTAs/SM, ~52KB L1 for the 32KB/layer B-slab).
// Retains: 2-mma split for hidden activations, paired-B uint4 image,
// in-place A, ldmatrix.x4, two-pass order, fused prep kernel, full syncs.
//
// Per CTA: 128 points, 256 threads = 8 warps (4 M-warps x 2 N-warps),
// warp wm owns rows 32*wm..32*wm+31 (m-tiles 2wm, 2wm+1).
// sigma folded into L8 (w23 padded to N=160; col 128 = sigma).
// Color head via mma (N pad 16). Output: color (3N) then sigma (N).
// ===========================================================================

constexpr int MPTS     = 128;
constexpr int NTHREADS = 256;

constexpr int AP = 136;   // A pitch (halves); 272B rows: 16B-aligned, bank-stride 4
constexpr int XP = 72;    // X pitch (halves)

// smem half-index offsets (A hi/lo split, X hi only)
constexpr int S_AHI = 0;
constexpr int S_ALO = S_AHI + MPTS * AP;      // 17408
constexpr int S_XHI = S_ALO + MPTS * AP;      // 34816
constexpr int SMEM_HALVES = S_XHI + MPTS * XP;  // 44032
constexpr int SMEM_BYTES  = SMEM_HALVES * 2;    // 88064 -> 2 CTAs/SM

// weight image section offsets (uint4 units); size = NKS*NTP*32
// uint4 = {bh0(nt),bh1(nt),bh0(nt+1),bh1(nt+1)} for n-tile pair ntp.
constexpr int O_L0   = 0;        // NKS4  NTP8  -> 1024
constexpr int O_L1   = 1024;     // NKS8  NTP8  -> 2048
constexpr int O_L2   = 3072;
constexpr int O_L3   = 5120;
constexpr int O_L4   = 7168;
constexpr int O_L5A  = 9216;     // 2048
constexpr int O_L5X  = 11264;    // NKS4  NTP8  -> 1024
constexpr int O_L6   = 12288;
constexpr int O_L7   = 14336;
constexpr int O_L8   = 16384;    // NKS8  NTP10 -> 2560 (N pad 160, col128=sigma)
constexpr int O_L9A  = 18944;    // NKS8  NTP4  -> 1024
constexpr int O_L9X  = 19968;    // NKS2  NTP4  -> 256
constexpr int O_HEAD = 20224;    // NKS4  NTP1  -> 128 (N pad 16)
constexpr int IMG_TOTAL = 20352; // uint4 -> 326 KB

__device__ uint4 g_img[IMG_TOTAL];

// ---------------- fused prep: pack paired per-lane B-hi fragments ----------
__device__ __forceinline__ uint32_t pack_h2(__half a, __half b) {
    __half2 v = __halves2half2(a, b);
    return *reinterpret_cast<uint32_t*>(&v);
}

__global__ void prep_all_kernel(
    const float* w10, const float* w11, const float* w12, const float* w13,
    const float* w14, const float* w20, const float* w21, const float* w22,
    const float* w23, const float* w30, const float* w31)
{
    int idx = blockIdx.x * blockDim.x + threadIdx.x;
    if (idx >= IMG_TOTAL) return;

    const int offs[14] = { O_L0, O_L1, O_L2, O_L3, O_L4, O_L5A, O_L5X,
                           O_L6, O_L7, O_L8, O_L9A, O_L9X, O_HEAD, IMG_TOTAL };
    const float* srcs[13] = { w10, w11, w12, w13, w14, w20, w20,
                              w21, w22, w23, w30, w30, w31 };
    //                       pitch kReal row0 nMax NTP
    const int cfg[13][5] = {
        { 128,  63,   0, 128,  8 },   // L0
        { 128, 128,   0, 128,  8 },   // L1
        { 128, 128,   0, 128,  8 },   // L2
        { 128, 128,   0, 128,  8 },   // L3
        { 128, 128,   0, 128,  8 },   // L4
        { 128, 128,   0, 128,  8 },   // L5A
        { 128,  63, 128, 128,  8 },   // L5X
        { 128, 128,   0, 128,  8 },   // L6
        { 128, 128,   0, 128,  8 },   // L7
        { 129, 128,   0, 129, 10 },   // L8
        {  64, 128,   0,  64,  4 },   // L9A
        {  64,  27, 128,  64,  4 },   // L9X
        {   3,  64,   0,   3,  1 },   // HEAD
    };

    int s = 0;
    while (idx >= offs[s + 1]) ++s;
    int local = idx - offs[s];
    const float* src = srcs[s];
    const int pitch = cfg[s][0], kReal = cfg[s][1], row0 = cfg[s][2];
    const int nMax  = cfg[s][3], NTP   = cfg[s][4];

    int lane = local & 31;
    int rest = local >> 5;
    int ntp  = rest % NTP;
    int ks   = rest / NTP;
    int g = lane >> 2, t = lane & 3;
    int kk[4] = { ks*16 + 2*t, ks*16 + 2*t + 1, ks*16 + 2*t + 8, ks*16 + 2*t + 9 };

    uint32_t packed[2][2];
    #pragma unroll
    for (int half = 0; half < 2; ++half) {
        int n = (ntp * 2 + half) * 8 + g;
        __half h[4];
        #pragma unroll
        for (int j = 0; j < 4; ++j) {
            float w = (kk[j] < kReal && n < nMax)
                        ? src[(row0 + kk[j]) * pitch + n] : 0.f;
            h[j] = __float2half_rn(w);
        }
        packed[half][0] = pack_h2(h[0], h[1]);
        packed[half][1] = pack_h2(h[2], h[3]);
    }
    g_img[idx] = make_uint4(packed[0][0], packed[0][1],
                            packed[1][0], packed[1][1]);
}

// ---------------- mma / ldmatrix -------------------------------------------
__device__ __forceinline__ uint32_t smem_u32(const void* p) {
    uint32_t a;
    asm("{ .reg .u64 t; cvta.to.shared.u64 t, %1; cvt.u32.u64 %0, t; }"
        : "=r"(a) : "l"(p));
    return a;
}

#define LDSM_X4(r, addr) \
    asm volatile("ldmatrix.sync.aligned.m8n8.x4.shared.b16 {%0,%1,%2,%3}, [%4];" \
        : "=r"((r)[0]), "=r"((r)[1]), "=r"((r)[2]), "=r"((r)[3]) : "r"(addr))

__device__ __forceinline__ void mma16816(float* c, const uint32_t* a,
                                         uint32_t b0, uint32_t b1) {
    asm volatile(
        "mma.sync.aligned.m16n8k16.row.col.f32.f16.f16.f32 "
        "{%0,%1,%2,%3}, {%4,%5,%6,%7}, {%8,%9}, {%0,%1,%2,%3};"
        : "+f"(c[0]), "+f"(c[1]), "+f"(c[2]), "+f"(c[3])
        : "r"(a[0]), "r"(a[1]), "r"(a[2]), "r"(a[3]), "r"(b0), "r"(b1));
}

// TWO m-tiles per warp. SPLIT: hidden act hi+lo (2 passes); else hi only.
// Per k-step one set of B LDGs feeds both m-tiles (8 mma per uint4 if SPLIT).
template <int NKS, int NT, bool SPLIT>
__device__ __forceinline__ void mma_loop2(
    float (*c0)[4], float (*c1)[4],
    const __half* Hi, const __half* Lo, int P,
    const uint4* __restrict__ img, int NTPG, int ntp0, int m0, int lane)
{
    constexpr int NP = NT / 2;
    const int mat = lane >> 3, rin = lane & 7;
    const int row = m0 + rin + 8 * (mat & 1);
    const int colk = 8 * (mat >> 1);
    const uint32_t aHi0 = smem_u32(Hi + row * P + colk);
    const uint32_t aHi1 = aHi0 + 16 * P * 2;     // +16 rows (bytes)
    const uint32_t aLo0 = SPLIT ? smem_u32(Lo + row * P + colk) : 0u;
    const uint32_t aLo1 = aLo0 + 16 * P * 2;
    #pragma unroll
    for (int ks = 0; ks < NKS; ++ks) {
        uint32_t ah0[4], ah1[4], al0[4], al1[4];
        if (SPLIT) {
            LDSM_X4(al0, aLo0 + ks * 32);
            LDSM_X4(al1, aLo1 + ks * 32);
        }
        LDSM_X4(ah0, aHi0 + ks * 32);
        LDSM_X4(ah1, aHi1 + ks * 32);
        const uint4* ib = img + (ks * NTPG + ntp0) * 32 + lane;
        uint4 b[NP];
        #pragma unroll
        for (int j = 0; j < NP; ++j) b[j] = __ldg(ib + j * 32);
        if (SPLIT) {
            #pragma unroll
            for (int j = 0; j < NP; ++j) {
                mma16816(c0[2*j],     al0, b[j].x, b[j].y);
                mma16816(c0[2*j + 1], al0, b[j].z, b[j].w);
                mma16816(c1[2*j],     al1, b[j].x, b[j].y);
                mma16816(c1[2*j + 1], al1, b[j].z, b[j].w);
            }
        }
        #pragma unroll
        for (int j = 0; j < NP; ++j) {
            mma16816(c0[2*j],     ah0, b[j].x, b[j].y);
            mma16816(c0[2*j + 1], ah0, b[j].z, b[j].w);
            mma16816(c1[2*j],     ah1, b[j].x, b[j].y);
            mma16816(c1[2*j + 1], ah1, b[j].z, b[j].w);
        }
    }
}

// Split-store a pair (cols col, col+1) at half-index idx (packed cvt).
__device__ __forceinline__ void store_split(__half* Hi, __half* Lo, int idx,
                                            float v0, float v1) {
    __half2 hp = __float22half2_rn(make_float2(v0, v1));
    float2 hf = __half22float2(hp);
    __half2 lp = __float22half2_rn(make_float2(v0 - hf.x, v1 - hf.y));
    *reinterpret_cast<__half2*>(Hi + idx) = hp;
    *reinterpret_cast<__half2*>(Lo + idx) = lp;
}

// Write 2 m-tiles x NT tiles into split A buffer.
template <int NT, bool RELU>
__device__ __forceinline__ void write_act2(
    float (*c0)[4], float (*c1)[4], __half* Hi, __half* Lo, int P,
    int nt0, int m0, int lane)
{
    const int g = lane >> 2, t = lane & 3;
    #pragma unroll
    for (int mi = 0; mi < 2; ++mi) {
        float (*c)[4] = mi ? c1 : c0;
        const int r0 = (m0 + 16 * mi + g) * P;
        const int r1 = r0 + 8 * P;
        #pragma unroll
        for (int nt = 0; nt < NT; ++nt) {
            int col = (nt0 + nt) * 8 + 2 * t;
            float v0 = c[nt][0], v1 = c[nt][1], v2 = c[nt][2], v3 = c[nt][3];
            if (RELU) {
                v0 = fmaxf(v0, 0.f); v1 = fmaxf(v1, 0.f);
                v2 = fmaxf(v2, 0.f); v3 = fmaxf(v3, 0.f);
            }
            store_split(Hi, Lo, r0 + col, v0, v1);
            store_split(Hi, Lo, r1 + col, v2, v3);
        }
    }
}

__device__ __forceinline__ void put_x(__half* XHi, int row, int col, float v) {
    XHi[row * XP + col] = __float2half_rn(v);
}

// ---------------- main kernel ----------------------------------------------
__global__ void __launch_bounds__(NTHREADS, 2)
ffnerf_hmma_kernel(const float* __restrict__ pos,
                   const float* __restrict__ dirs,
                   float* __restrict__ out, int npts)
{
    extern __shared__ __half smh[];
    __half* AHi = smh + S_AHI;
    __half* ALo = smh + S_ALO;
    __half* XHi = smh + S_XHI;

    const int tid  = threadIdx.x;
    const int lane = tid & 31;
    const int warp = tid >> 5;
    const int g    = lane >> 2;
    const int t    = lane & 3;
    const int wm   = warp & 3;
    const int wn   = warp >> 2;
    const int m0   = wm * 32;         // two m-tiles: m0, m0+16
    const int g0   = blockIdx.x * MPTS;

    // --- posenc x_emb (63 features, col 63 zero), hi only ------------------
    if (tid < MPTS) {
        int gp = g0 + tid;
        float p0 = pos[gp*3+0], p1 = pos[gp*3+1], p2 = pos[gp*3+2];
        put_x(XHi, tid, 0, p0);
        put_x(XHi, tid, 1, p1);
        put_x(XHi, tid, 2, p2);
        #pragma unroll
        for (int j = 0; j < 10; ++j) {
            float f = (float)(1 << j);
            float s0, c0, s1, c1, s2, c2;
            sincosf(f * p0, &s0, &c0);
            sincosf(f * p1, &s1, &c1);
            sincosf(f * p2, &s2, &c2);
            put_x(XHi, tid, 3 + 6*j + 0, s0);
            put_x(XHi, tid, 3 + 6*j + 1, s1);
            put_x(XHi, tid, 3 + 6*j + 2, s2);
            put_x(XHi, tid, 3 + 6*j + 3, c0);
            put_x(XHi, tid, 3 + 6*j + 4, c1);
            put_x(XHi, tid, 3 + 6*j + 5, c2);
        }
        put_x(XHi, tid, 63, 0.f);
    }
    __syncthreads();

    // --- L0: x_emb(64) -> 128, relu (X hi only: single pass) ---------------
    {
        float c0[8][4], c1[8][4];
        #pragma unroll
        for (int i = 0; i < 8; ++i)
            #pragma unroll
            for (int j = 0; j < 4; ++j) { c0[i][j] = 0.f; c1[i][j] = 0.f; }
        mma_loop2<4, 8, false>(c0, c1, XHi, nullptr, XP,
                               g_img + O_L0, 8, wn * 4, m0, lane);
        write_act2<8, true>(c0, c1, AHi, ALo, AP, wn * 8, m0, lane);
        __syncthreads();
    }

    // --- L1..L4: 128 -> 128, relu (in-place A) -----------------------------
    const int mids[4] = { O_L1, O_L2, O_L3, O_L4 };
    #pragma unroll
    for (int li = 0; li < 4; ++li) {
        float c0[8][4], c1[8][4];
        #pragma unroll
        for (int i = 0; i < 8; ++i)
            #pragma unroll
            for (int j = 0; j < 4; ++j) { c0[i][j] = 0.f; c1[i][j] = 0.f; }
        mma_loop2<8, 8, true>(c0, c1, AHi, ALo, AP,
                              g_img + mids[li], 8, wn * 4, m0, lane);
        __syncthreads();
        write_act2<8, true>(c0, c1, AHi, ALo, AP, wn * 8, m0, lane);
        __syncthreads();
    }

    // --- L5: [h | x_emb](192) -> 128, relu; then d_emb into X --------------
    {
        float c0[8][4], c1[8][4];
        #pragma unroll
        for (int i = 0; i < 8; ++i)
            #pragma unroll
            for (int j = 0; j < 4; ++j) { c0[i][j] = 0.f; c1[i][j] = 0.f; }
        mma_loop2<8, 8, true>(c0, c1, AHi, ALo, AP,
                              g_img + O_L5A, 8, wn * 4, m0, lane);
        mma_loop2<4, 8, false>(c0, c1, XHi, nullptr, XP,
                               g_img + O_L5X, 8, wn * 4, m0, lane);
        __syncthreads();
        write_act2<8, true>(c0, c1, AHi, ALo, AP, wn * 8, m0, lane);
        // d_emb posenc (27 features, cols 27..31 zero), hi only
        if (tid < MPTS) {
            int gp = g0 + tid;
            float d0 = dirs[gp*3+0], d1 = dirs[gp*3+1], d2 = dirs[gp*3+2];
            put_x(XHi, tid, 0, d0);
            put_x(XHi, tid, 1, d1);
            put_x(XHi, tid, 2, d2);
            #pragma unroll
            for (int j = 0; j < 4; ++j) {
                float f = (float)(1 << j);
                float s0, c0f, s1, c1f, s2, c2f;
                sincosf(f * d0, &s0, &c0f);
                sincosf(f * d1, &s1, &c1f);
                sincosf(f * d2, &s2, &c2f);
                put_x(XHi, tid, 3 + 6*j + 0, s0);
                put_x(XHi, tid, 3 + 6*j + 1, s1);
                put_x(XHi, tid, 3 + 6*j + 2, s2);
                put_x(XHi, tid, 3 + 6*j + 3, c0f);
                put_x(XHi, tid, 3 + 6*j + 4, c1f);
                put_x(XHi, tid, 3 + 6*j + 5, c2f);
            }
            #pragma unroll
            for (int z = 27; z < 32; ++z) put_x(XHi, tid, z, 0.f);
        }
        __syncthreads();
    }

    // --- L6, L7: 128 -> 128, relu ------------------------------------------
    #pragma unroll
    for (int li = 0; li < 2; ++li) {
        float c0[8][4], c1[8][4];
        #pragma unroll
        for (int i = 0; i < 8; ++i)
            #pragma unroll
            for (int j = 0; j < 4; ++j) { c0[i][j] = 0.f; c1[i][j] = 0.f; }
        mma_loop2<8, 8, true>(c0, c1, AHi, ALo, AP,
                              g_img + (li == 0 ? O_L6 : O_L7), 8,
                              wn * 4, m0, lane);
        __syncthreads();
        write_act2<8, true>(c0, c1, AHi, ALo, AP, wn * 8, m0, lane);
        __syncthreads();
    }

    // --- L8: 128 -> 160-pad (feat cols 0..127 linear, col 128 = sigma) -----
    {
        float c0[10][4], c1[10][4];
        #pragma unroll
        for (int i = 0; i < 10; ++i)
            #pragma unroll
            for (int j = 0; j < 4; ++j) { c0[i][j] = 0.f; c1[i][j] = 0.f; }
        mma_loop2<8, 10, true>(c0, c1, AHi, ALo, AP,
                               g_img + O_L8, 10, wn * 5, m0, lane);
        __syncthreads();
        float* sigma = out + (size_t)3 * npts + g0;
        #pragma unroll
        for (int mi = 0; mi < 2; ++mi) {
            float (*c)[4] = mi ? c1 : c0;
            const int r0 = (m0 + 16 * mi + g) * AP;
            const int r1 = r0 + 8 * AP;
            #pragma unroll
            for (int nt = 0; nt < 10; ++nt) {
                int colb = (wn * 10 + nt) * 8;
                if (colb < 128) {                       // feat, linear
                    int col = colb + 2 * t;
                    store_split(AHi, ALo, r0 + col, c[nt][0], c[nt][1]);
                    store_split(AHi, ALo, r1 + col, c[nt][2], c[nt][3]);
                } else if (colb == 128 && t == 0) {     // sigma column
                    sigma[m0 + 16 * mi + g]     = fmaxf(c[nt][0], 0.f);
                    sigma[m0 + 16 * mi + g + 8] = fmaxf(c[nt][2], 0.f);
                }
            }
        }
        __syncthreads();
    }

    // --- L9: [feat | d_emb] -> 64, relu ------------------------------------
    {
        float c0[4][4], c1[4][4];
        #pragma unroll
        for (int i = 0; i < 4; ++i)
            #pragma unroll
            for (int j = 0; j < 4; ++j) { c0[i][j] = 0.f; c1[i][j] = 0.f; }
        mma_loop2<8, 4, true>(c0, c1, AHi, ALo, AP,
                              g_img + O_L9A, 4, wn * 2, m0, lane);
        mma_loop2<2, 4, false>(c0, c1, XHi, nullptr, XP,
                               g_img + O_L9X, 4, wn * 2, m0, lane);
        __syncthreads();
        write_act2<4, true>(c0, c1, AHi, ALo, AP, wn * 4, m0, lane);
        __syncthreads();
    }

    // --- head: 64 -> 3 (pad 16), sigmoid -> color --------------------------
    if (wn == 0) {
        float c0[2][4], c1[2][4];
        #pragma unroll
        for (int i = 0; i < 2; ++i)
            #pragma unroll
            for (int j = 0; j < 4; ++j) { c0[i][j] = 0.f; c1[i][j] = 0.f; }
        mma_loop2<4, 2, true>(c0, c1, AHi, ALo, AP,
                              g_img + O_HEAD, 1, 0, m0, lane);
        #pragma unroll
        for (int mi = 0; mi < 2; ++mi) {
            float (*c)[4] = mi ? c1 : c0;
            int row0 = g0 + m0 + 16 * mi + g;
            int row1 = row0 + 8;
            if (t == 0) {
                out[row0*3 + 0] = 1.f / (1.f + expf(-c[0][0]));
                out[row0*3 + 1] = 1.f / (1.f + expf(-c[0][1]));
                out[row1*3 + 0] = 1.f / (1.f + expf(-c[0][2]));
                out[row1*3 + 1] = 1.f / (1.f + expf(-c[0][3]));
            } else if (t == 1) {
                out[row0*3 + 2] = 1.f / (1.f + expf(-c[0][0]));
                out[row1*3 + 2] = 1.f / (1.f + expf(-c[0][2]));
            }
        }
    }
}

// ---------------- launch ----------------------------------------------------
extern "C" void kernel_launch(void* const* d_in, const int* in_sizes, int n_in,
                              void* d_out, int out_size)
{
    const float* pos  = (const float*)d_in[0];
    const float* dirs = (const float*)d_in[1];
    const float* w10  = (const float*)d_in[2];
    const float* w11  = (const float*)d_in[3];
    const float* w12  = (const float*)d_in[4];
    const float* w13  = (const float*)d_in[5];
    const float* w14  = (const float*)d_in[6];
    const float* w20  = (const float*)d_in[7];
    const float* w21  = (const float*)d_in[8];
    const float* w22  = (const float*)d_in[9];
    const float* w23  = (const float*)d_in[10];
    const float* w30  = (const float*)d_in[11];
    const float* w31  = (const float*)d_in[12];

    int npts = in_sizes[0] / 3;
    int nblocks = npts / MPTS;

    prep_all_kernel<<<(IMG_TOTAL + 255) / 256, 256>>>(
        w10, w11, w12, w13, w14, w20, w21, w22, w23, w30, w31);

    cudaFuncSetAttribute(ffnerf_hmma_kernel,
                         cudaFuncAttributeMaxDynamicSharedMemorySize, SMEM_BYTES);
    ffnerf_hmma_kernel<<<nblocks, NTHREADS, SMEM_BYTES>>>(
        pos, dirs, (float*)d_out, npts);
    (void)n_in; (void)out_size;
}